// round 9
// baseline (speedup 1.0000x reference)
#include <cuda_runtime.h>
#include <cuda_bf16.h>
#include <cstdint>
#include <math.h>

#define BB 2
#define CC 512
#define NN 4096
#define NGROUPS 32
#define CPG 16
#define EPS 1e-6f

typedef __nv_bfloat16 bf16;
typedef __nv_bfloat162 bf162;

// ---------------- scratch globals ----------------
__device__ bf16 g_ht_hi[(size_t)BB * NN * CC], g_ht_lo[(size_t)BB * NN * CC];   // h^T [b][n][c]
__device__ bf16 g_qt_hi[(size_t)BB * NN * CC], g_qt_lo[(size_t)BB * NN * CC];   // q^T [b][n][c]
__device__ bf16 g_kt_hi[(size_t)BB * NN * CC], g_kt_lo[(size_t)BB * NN * CC];
__device__ bf16 g_v_hi [(size_t)BB * CC * NN], g_v_lo [(size_t)BB * CC * NN];   // v [b][c][n]
__device__ bf16 g_ot_hi[(size_t)BB * NN * CC], g_ot_lo[(size_t)BB * NN * CC];   // o^T [b][n][c]
__device__ bf16 g_wq_hi[CC * CC], g_wq_lo[CC * CC];
__device__ bf16 g_wk_hi[CC * CC], g_wk_lo[CC * CC];
__device__ bf16 g_wv_hi[CC * CC], g_wv_lo[CC * CC];
__device__ bf16 g_wo_hi[CC * CC], g_wo_lo[CC * CC];
__device__ float g_s[(size_t)BB * NN * NN];                                      // logits
__device__ bf16 g_p_hi[(size_t)BB * NN * NN], g_p_lo[(size_t)BB * NN * NN];     // probs

// ---------------- PTX helpers ----------------
__device__ __forceinline__ uint32_t smem_u32(const void* p) {
    uint32_t a;
    asm("{ .reg .u64 t; cvta.to.shared.u64 t, %1; cvt.u32.u64 %0, t; }" : "=r"(a) : "l"(p));
    return a;
}
__device__ __forceinline__ void cp16(uint32_t saddr, const void* g) {
    asm volatile("cp.async.cg.shared.global [%0], [%1], 16;" :: "r"(saddr), "l"(g) : "memory");
}
#define CP_COMMIT() asm volatile("cp.async.commit_group;" ::: "memory")
#define CP_WAIT(n)  asm volatile("cp.async.wait_group %0;" :: "n"(n) : "memory")

__device__ __forceinline__ void ldm_x4(uint32_t* r, uint32_t addr) {
    asm volatile("ldmatrix.sync.aligned.m8n8.x4.shared.b16 {%0,%1,%2,%3}, [%4];"
        : "=r"(r[0]), "=r"(r[1]), "=r"(r[2]), "=r"(r[3]) : "r"(addr));
}
__device__ __forceinline__ void mma_bf16(float* d, const uint32_t* a, const uint32_t* b) {
    asm volatile("mma.sync.aligned.m16n8k16.row.col.f32.bf16.bf16.f32 "
        "{%0,%1,%2,%3}, {%4,%5,%6,%7}, {%8,%9}, {%0,%1,%2,%3};"
        : "+f"(d[0]), "+f"(d[1]), "+f"(d[2]), "+f"(d[3])
        : "r"(a[0]), "r"(a[1]), "r"(a[2]), "r"(a[3]), "r"(b[0]), "r"(b[1]));
}
#define SWZ64(o) ((o) ^ (((o) >> 3) & 0x30))

// ---------------- GroupNorm -> h^T hi/lo ----------------
__global__ void gn_kernel(const float* __restrict__ x,
                          const float* __restrict__ gamma,
                          const float* __restrict__ beta) {
    __shared__ float tile[16][257];
    __shared__ float red[8], red2[8];
    __shared__ float sga[16], sbe[16], s_mean, s_rstd;
    const int bg = blockIdx.x, b = bg >> 5, g = bg & 31;
    const size_t xbase = ((size_t)b * CC + (size_t)g * CPG) * NN;
    const float* xp = x + xbase;
    const int tid = threadIdx.x;
    if (tid < 16) { sga[tid] = gamma[g * CPG + tid]; sbe[tid] = beta[g * CPG + tid]; }

    float s = 0.f, ss = 0.f;
    for (int i = tid * 4; i < CPG * NN; i += 1024) {
        float4 v = *reinterpret_cast<const float4*>(xp + i);
        s += v.x + v.y + v.z + v.w;
        ss += v.x * v.x + v.y * v.y + v.z * v.z + v.w * v.w;
    }
    #pragma unroll
    for (int o = 16; o; o >>= 1) {
        s += __shfl_xor_sync(0xffffffffu, s, o);
        ss += __shfl_xor_sync(0xffffffffu, ss, o);
    }
    if ((tid & 31) == 0) { red[tid >> 5] = s; red2[tid >> 5] = ss; }
    __syncthreads();
    if (tid == 0) {
        float S = 0.f, SS = 0.f;
        for (int i = 0; i < 8; i++) { S += red[i]; SS += red2[i]; }
        float mean = S / (float)(CPG * NN);
        s_mean = mean;
        s_rstd = rsqrtf(SS / (float)(CPG * NN) - mean * mean + EPS);
    }
    __syncthreads();
    const float mean = s_mean, rstd = s_rstd;

    for (int n0 = 0; n0 < NN; n0 += 256) {
        __syncthreads();
        for (int i = tid; i < 16 * 256; i += 256) {
            int c = i >> 8, n = i & 255;
            tile[c][n] = xp[(size_t)c * NN + n0 + n];
        }
        __syncthreads();
        const int n = n0 + tid;
        __align__(16) bf162 hv[8], lv[8];
        #pragma unroll
        for (int c2 = 0; c2 < 8; c2++) {
            float v0 = (tile[2 * c2][tid] - mean) * rstd * sga[2 * c2] + sbe[2 * c2];
            float v1 = (tile[2 * c2 + 1][tid] - mean) * rstd * sga[2 * c2 + 1] + sbe[2 * c2 + 1];
            bf16 h0 = __float2bfloat16(v0), h1 = __float2bfloat16(v1);
            hv[c2] = __halves2bfloat162(h0, h1);
            lv[c2] = __halves2bfloat162(__float2bfloat16(v0 - __bfloat162float(h0)),
                                        __float2bfloat16(v1 - __bfloat162float(h1)));
        }
        const size_t dst = ((size_t)b * NN + n) * CC + (size_t)g * CPG;
        *reinterpret_cast<uint4*>(g_ht_hi + dst)     = reinterpret_cast<uint4*>(hv)[0];
        *reinterpret_cast<uint4*>(g_ht_hi + dst + 8) = reinterpret_cast<uint4*>(hv)[1];
        *reinterpret_cast<uint4*>(g_ht_lo + dst)     = reinterpret_cast<uint4*>(lv)[0];
        *reinterpret_cast<uint4*>(g_ht_lo + dst + 8) = reinterpret_cast<uint4*>(lv)[1];
    }
}

// ---------------- fused weight hi/lo decomposition ----------------
__global__ void decomp4_kernel(const float* __restrict__ w0, const float* __restrict__ w1,
                               const float* __restrict__ w2, const float* __restrict__ w3) {
    const int wsel = blockIdx.y;
    const float* src = (wsel == 0) ? w0 : (wsel == 1) ? w1 : (wsel == 2) ? w2 : w3;
    bf16* hi = (wsel == 0) ? g_wq_hi : (wsel == 1) ? g_wk_hi : (wsel == 2) ? g_wv_hi : g_wo_hi;
    bf16* lo = (wsel == 0) ? g_wq_lo : (wsel == 1) ? g_wk_lo : (wsel == 2) ? g_wv_lo : g_wo_lo;
    int i = blockIdx.x * blockDim.x + threadIdx.x;
    if (i >= (CC * CC) / 4) return;
    float4 v = reinterpret_cast<const float4*>(src)[i];
    bf16 h0 = __float2bfloat16(v.x), h1 = __float2bfloat16(v.y);
    bf16 h2 = __float2bfloat16(v.z), h3 = __float2bfloat16(v.w);
    __align__(8) bf162 hv[2] = { __halves2bfloat162(h0, h1), __halves2bfloat162(h2, h3) };
    __align__(8) bf162 lv[2] = {
        __halves2bfloat162(__float2bfloat16(v.x - __bfloat162float(h0)),
                           __float2bfloat16(v.y - __bfloat162float(h1))),
        __halves2bfloat162(__float2bfloat16(v.z - __bfloat162float(h2)),
                           __float2bfloat16(v.w - __bfloat162float(h3))) };
    *reinterpret_cast<uint2*>(hi + 4 * (size_t)i) = *reinterpret_cast<uint2*>(hv);
    *reinterpret_cast<uint2*>(lo + 4 * (size_t)i) = *reinterpret_cast<uint2*>(lv);
}

// ---------------- softmax (per batch): fp32 logits -> bf16 hi/lo probs ------
__global__ void softmax_kernel(const float* __restrict__ sbase,
                               bf16* __restrict__ phi, bf16* __restrict__ plo) {
    __shared__ float row[NN];
    __shared__ float red[8];
    __shared__ float s_bcast;
    const size_t rbase = (size_t)blockIdx.x * NN;
    const float* sp = sbase + rbase;
    const int tid = threadIdx.x;

    float mx = -1e30f;
    for (int i = tid * 4; i < NN; i += 1024) {
        float4 v = *reinterpret_cast<const float4*>(sp + i);
        *reinterpret_cast<float4*>(row + i) = v;
        mx = fmaxf(fmaxf(v.x, v.y), fmaxf(fmaxf(v.z, v.w), mx));
    }
    #pragma unroll
    for (int o = 16; o; o >>= 1) mx = fmaxf(mx, __shfl_xor_sync(0xffffffffu, mx, o));
    if ((tid & 31) == 0) red[tid >> 5] = mx;
    __syncthreads();
    if (tid == 0) {
        float m = red[0];
        for (int i = 1; i < 8; i++) m = fmaxf(m, red[i]);
        s_bcast = m;
    }
    __syncthreads();
    mx = s_bcast;
    __syncthreads();

    float s = 0.f;
    for (int i = tid * 4; i < NN; i += 1024) {
        float4 v = *reinterpret_cast<float4*>(row + i);
        v.x = __expf(v.x - mx); v.y = __expf(v.y - mx);
        v.z = __expf(v.z - mx); v.w = __expf(v.w - mx);
        *reinterpret_cast<float4*>(row + i) = v;
        s += v.x + v.y + v.z + v.w;
    }
    #pragma unroll
    for (int o = 16; o; o >>= 1) s += __shfl_xor_sync(0xffffffffu, s, o);
    if ((tid & 31) == 0) red[tid >> 5] = s;
    __syncthreads();
    if (tid == 0) {
        float S = 0.f;
        for (int i = 0; i < 8; i++) S += red[i];
        s_bcast = 1.0f / S;
    }
    __syncthreads();
    const float inv = s_bcast;

    for (int i = tid * 4; i < NN; i += 1024) {
        float4 v = *reinterpret_cast<float4*>(row + i);
        float p0 = v.x * inv, p1 = v.y * inv, p2 = v.z * inv, p3 = v.w * inv;
        bf16 h0 = __float2bfloat16(p0), h1 = __float2bfloat16(p1);
        bf16 h2 = __float2bfloat16(p2), h3 = __float2bfloat16(p3);
        __align__(8) bf162 hv[2] = { __halves2bfloat162(h0, h1), __halves2bfloat162(h2, h3) };
        __align__(8) bf162 lv[2] = {
            __halves2bfloat162(__float2bfloat16(p0 - __bfloat162float(h0)),
                               __float2bfloat16(p1 - __bfloat162float(h1))),
            __halves2bfloat162(__float2bfloat16(p2 - __bfloat162float(h2)),
                               __float2bfloat16(p3 - __bfloat162float(h3))) };
        *reinterpret_cast<uint2*>(phi + rbase + i) = *reinterpret_cast<uint2*>(hv);
        *reinterpret_cast<uint2*>(plo + rbase + i) = *reinterpret_cast<uint2*>(lv);
    }
}

// ---------------- HMMA bf16x3 GEMM core: 128(M)x256(N), BK=32, 4-stage -----
#define A_T 8192                          // 128x32 bf16
#define B_T 16384                         // 256x32 bf16
#define ST_AH 0
#define ST_AL A_T
#define ST_BH (2 * A_T)
#define ST_BL (2 * A_T + B_T)
#define STAGE_B (2 * A_T + 2 * B_T)       // 49152
#define NSTAGE 4
#define SMEM_TOTAL (NSTAGE * STAGE_B)     // 196608

__device__ __forceinline__ void loadA(const bf16* __restrict__ src, int row0, int ld,
                                      int k0, uint32_t sdst, int tid) {
    #pragma unroll
    for (int i = 0; i < 2; i++) {
        int c = tid + i * 256;
        int r = c >> 2, ck = c & 3;
        cp16(sdst + SWZ64((uint32_t)(r * 64 + ck * 16)),
             src + (size_t)(row0 + r) * ld + k0 + ck * 8);
    }
}
__device__ __forceinline__ void loadB(const bf16* __restrict__ src, int row0, int ld,
                                      int k0, uint32_t sdst, int tid) {
    #pragma unroll
    for (int i = 0; i < 4; i++) {
        int c = tid + i * 256;
        int r = c >> 2, ck = c & 3;
        cp16(sdst + SWZ64((uint32_t)(r * 64 + ck * 16)),
             src + (size_t)(row0 + r) * ld + k0 + ck * 8);
    }
}

__device__ __forceinline__ void gemm_core(
        const bf16* __restrict__ pAh, const bf16* __restrict__ pAl,
        const bf16* __restrict__ pBh, const bf16* __restrict__ pBl,
        int lda, int ldb, int K, int m0, int n0,
        float* __restrict__ Cf, bf16* __restrict__ Chi, bf16* __restrict__ Clo,
        int ldc, const float* __restrict__ bias, int bias_mode,
        const float* __restrict__ resid, float scale, char* smem) {
    const uint32_t sb = smem_u32(smem);
    const int tid = threadIdx.x, wid = tid >> 5, lane = tid & 31;
    const int wm0 = (wid & 1) * 64, wn0 = (wid >> 1) * 64;
    const int NC = K >> 5;
    float acc[4][8][4] = {};

    // prologue: 3 chunks
    #pragma unroll
    for (int p = 0; p < 3; p++) {
        uint32_t base = sb + p * STAGE_B;
        loadA(pAh, m0, lda, p * 32, base + ST_AH, tid);
        loadA(pAl, m0, lda, p * 32, base + ST_AL, tid);
        loadB(pBh, n0, ldb, p * 32, base + ST_BH, tid);
        loadB(pBl, n0, ldb, p * 32, base + ST_BL, tid);
        CP_COMMIT();
    }

    int st = 0;
    for (int c = 0; c < NC; c++) {
        CP_WAIT(2);
        __syncthreads();
        if (c + 3 < NC) {
            int st2 = st + 3; if (st2 >= NSTAGE) st2 -= NSTAGE;
            uint32_t base = sb + st2 * STAGE_B;
            const int k0 = (c + 3) << 5;
            loadA(pAh, m0, lda, k0, base + ST_AH, tid);
            loadA(pAl, m0, lda, k0, base + ST_AL, tid);
            loadB(pBh, n0, ldb, k0, base + ST_BH, tid);
            loadB(pBl, n0, ldb, k0, base + ST_BL, tid);
        }
        CP_COMMIT();

        const uint32_t base = sb + st * STAGE_B;
        #pragma unroll
        for (int ks = 0; ks < 2; ks++) {
            uint32_t bhi[4][4], blo[4][4];
            #pragma unroll
            for (int nt2 = 0; nt2 < 4; nt2++) {
                const uint32_t off = SWZ64((uint32_t)(
                    (wn0 + nt2 * 16 + ((lane >> 4) & 1) * 8 + (lane & 7)) * 64 +
                    ks * 32 + ((lane >> 3) & 1) * 16));
                ldm_x4(bhi[nt2], base + ST_BH + off);
                ldm_x4(blo[nt2], base + ST_BL + off);
            }
            #pragma unroll
            for (int mt = 0; mt < 4; mt++) {
                uint32_t ahi[4], alo[4];
                const uint32_t off = SWZ64((uint32_t)(
                    (wm0 + mt * 16 + (lane & 15)) * 64 + ks * 32 + (lane >> 4) * 16));
                ldm_x4(ahi, base + ST_AH + off);
                ldm_x4(alo, base + ST_AL + off);
                #pragma unroll
                for (int nt = 0; nt < 8; nt++) {
                    const uint32_t* bh = &bhi[nt >> 1][(nt & 1) * 2];
                    const uint32_t* bl = &blo[nt >> 1][(nt & 1) * 2];
                    mma_bf16(acc[mt][nt], ahi, bh);
                    mma_bf16(acc[mt][nt], ahi, bl);
                    mma_bf16(acc[mt][nt], alo, bh);
                }
            }
        }
        st++; if (st >= NSTAGE) st = 0;
    }

    // epilogue
    const int r0 = lane >> 2, cp2 = (lane & 3) * 2;
    #pragma unroll
    for (int mt = 0; mt < 4; mt++) {
        #pragma unroll
        for (int half = 0; half < 2; half++) {
            const int gm = m0 + wm0 + mt * 16 + r0 + half * 8;
            const float bm = (bias_mode == 1) ? bias[gm] : 0.f;
            #pragma unroll
            for (int nt = 0; nt < 8; nt++) {
                const int gn = n0 + wn0 + nt * 8 + cp2;
                float v0 = acc[mt][nt][half * 2 + 0] * scale + bm;
                float v1 = acc[mt][nt][half * 2 + 1] * scale + bm;
                if (bias_mode == 2) { v0 += bias[gn]; v1 += bias[gn + 1]; }
                const size_t idx = (size_t)gm * ldc + gn;
                if (Cf) {
                    if (resid) { v0 += resid[idx]; v1 += resid[idx + 1]; }
                    float2 o = { v0, v1 };
                    *reinterpret_cast<float2*>(Cf + idx) = o;
                } else {
                    bf16 h0 = __float2bfloat16(v0), h1 = __float2bfloat16(v1);
                    bf162 hv = __halves2bfloat162(h0, h1);
                    bf162 lv = __halves2bfloat162(__float2bfloat16(v0 - __bfloat162float(h0)),
                                                  __float2bfloat16(v1 - __bfloat162float(h1)));
                    *reinterpret_cast<bf162*>(Chi + idx) = hv;
                    *reinterpret_cast<bf162*>(Clo + idx) = lv;
                }
            }
        }
    }
}

// Generic single-job wrapper (batch pre-offset on host)
__global__ void __launch_bounds__(256)
mma_gemm(const bf16* __restrict__ Ah, const bf16* __restrict__ Al,
         const bf16* __restrict__ Bh, const bf16* __restrict__ Bl,
         int lda, int ldb, int K,
         float* __restrict__ Cf, bf16* __restrict__ Chi, bf16* __restrict__ Clo,
         int ldc, const float* __restrict__ bias, int bias_mode,
         const float* __restrict__ resid, float scale) {
    extern __shared__ __align__(1024) char smem[];
    gemm_core(Ah, Al, Bh, Bl, lda, ldb, K, blockIdx.y * 128, blockIdx.x * 256,
              Cf, Chi, Clo, ldc, bias, bias_mode, resid, scale, smem);
}

// Q/K projections: grid (2, 32, 4): z -> (b, op)
__global__ void __launch_bounds__(256)
qk_gemm(const float* __restrict__ bq, const float* __restrict__ bk) {
    extern __shared__ __align__(1024) char smem[];
    const int b = blockIdx.z >> 1, op = blockIdx.z & 1;
    const size_t sNC = (size_t)NN * CC;
    const bf16* hth = g_ht_hi + (size_t)b * sNC;
    const bf16* htl = g_ht_lo + (size_t)b * sNC;
    const bf16* wh = op ? g_wk_hi : g_wq_hi;
    const bf16* wl = op ? g_wk_lo : g_wq_lo;
    bf16* ch = (op ? g_kt_hi : g_qt_hi) + (size_t)b * sNC;
    bf16* cl = (op ? g_kt_lo : g_qt_lo) + (size_t)b * sNC;
    gemm_core(hth, htl, wh, wl, CC, CC, CC, blockIdx.y * 128, blockIdx.x * 256,
              nullptr, ch, cl, CC, op ? bk : bq, 2, nullptr, 1.f, smem);
}

// V projection: grid (16, 4, 2): z = b
__global__ void __launch_bounds__(256)
v_gemm(const float* __restrict__ bv) {
    extern __shared__ __align__(1024) char smem[];
    const int b = blockIdx.z;
    const size_t sNC = (size_t)NN * CC, sCN = (size_t)CC * NN;
    gemm_core(g_wv_hi, g_wv_lo,
              g_ht_hi + (size_t)b * sNC, g_ht_lo + (size_t)b * sNC,
              CC, CC, CC, blockIdx.y * 128, blockIdx.x * 256,
              nullptr, g_v_hi + (size_t)b * sCN, g_v_lo + (size_t)b * sCN,
              NN, bv, 1, nullptr, 1.f, smem);
}

// ---------------- launch ----------------
#define SYM(p, s) do { void* _t = nullptr; cudaGetSymbolAddress(&_t, s); p = (decltype(p))_t; } while (0)

extern "C" void kernel_launch(void* const* d_in, const int* in_sizes, int n_in,
                              void* d_out, int out_size) {
    const float* x     = (const float*)d_in[0];
    const float* gamma = (const float*)d_in[1];
    const float* beta  = (const float*)d_in[2];
    const float* wq = (const float*)d_in[3];
    const float* bq = (const float*)d_in[4];
    const float* wk = (const float*)d_in[5];
    const float* bk = (const float*)d_in[6];
    const float* wv = (const float*)d_in[7];
    const float* bv = (const float*)d_in[8];
    const float* wo = (const float*)d_in[9];
    const float* bo = (const float*)d_in[10];
    float* out = (float*)d_out;

    bf16 *qt_h, *qt_l, *kt_h, *kt_l, *v_h, *v_l, *ot_h, *ot_l;
    bf16 *wo_h, *wo_l, *p_h, *p_l;
    float* s_ptr;
    SYM(qt_h, g_qt_hi); SYM(qt_l, g_qt_lo);
    SYM(kt_h, g_kt_hi); SYM(kt_l, g_kt_lo);
    SYM(v_h, g_v_hi);   SYM(v_l, g_v_lo);
    SYM(ot_h, g_ot_hi); SYM(ot_l, g_ot_lo);
    SYM(wo_h, g_wo_hi); SYM(wo_l, g_wo_lo);
    SYM(p_h, g_p_hi);   SYM(p_l, g_p_lo);
    SYM(s_ptr, g_s);

    static bool inited = false;
    static cudaStream_t s1, s2;
    static cudaEvent_t eFork, eGn, eD1, eV, eS0, eS1, eSm0, eSm1, eDone1, eDone2;
    if (!inited) {
        cudaStreamCreateWithFlags(&s1, cudaStreamNonBlocking);
        cudaStreamCreateWithFlags(&s2, cudaStreamNonBlocking);
        cudaEventCreateWithFlags(&eFork,  cudaEventDisableTiming);
        cudaEventCreateWithFlags(&eGn,    cudaEventDisableTiming);
        cudaEventCreateWithFlags(&eD1,    cudaEventDisableTiming);
        cudaEventCreateWithFlags(&eV,     cudaEventDisableTiming);
        cudaEventCreateWithFlags(&eS0,    cudaEventDisableTiming);
        cudaEventCreateWithFlags(&eS1,    cudaEventDisableTiming);
        cudaEventCreateWithFlags(&eSm0,   cudaEventDisableTiming);
        cudaEventCreateWithFlags(&eSm1,   cudaEventDisableTiming);
        cudaEventCreateWithFlags(&eDone1, cudaEventDisableTiming);
        cudaEventCreateWithFlags(&eDone2, cudaEventDisableTiming);
        cudaFuncSetAttribute(mma_gemm, cudaFuncAttributeMaxDynamicSharedMemorySize, SMEM_TOTAL);
        cudaFuncSetAttribute(qk_gemm,  cudaFuncAttributeMaxDynamicSharedMemorySize, SMEM_TOTAL);
        cudaFuncSetAttribute(v_gemm,   cudaFuncAttributeMaxDynamicSharedMemorySize, SMEM_TOTAL);
        inited = true;
    }

    const size_t sNC = (size_t)NN * CC, sCN = (size_t)CC * NN, sSS = (size_t)NN * NN;

    // fork both worker streams off the (capturing) default stream
    cudaEventRecord(eFork, 0);
    cudaStreamWaitEvent(s1, eFork, 0);
    cudaStreamWaitEvent(s2, eFork, 0);

    // s2: groupnorm  |  s1: weight decomposition (independent)
    gn_kernel<<<BB * NGROUPS, 256, 0, s2>>>(x, gamma, beta);
    cudaEventRecord(eGn, s2);
    decomp4_kernel<<<dim3((CC * CC / 4 + 255) / 256, 4), 256, 0, s1>>>(wq, wk, wv, wo);
    cudaEventRecord(eD1, s1);

    // s1: Q,K projections (needs gn + decomp)
    cudaStreamWaitEvent(s1, eGn, 0);
    qk_gemm<<<dim3(2, 32, 4), 256, SMEM_TOTAL, s1>>>(bq, bk);

    // s2: V projection (needs gn [in-stream] + decomp)
    cudaStreamWaitEvent(s2, eD1, 0);
    v_gemm<<<dim3(16, 4, 2), 256, SMEM_TOTAL, s2>>>(bv);
    cudaEventRecord(eV, s2);

    // s1: S per batch
    const float sscale = 0.044194173824159216f;
    mma_gemm<<<dim3(16, 32), 256, SMEM_TOTAL, s1>>>(qt_h, qt_l, kt_h, kt_l, CC, CC, CC,
        s_ptr, nullptr, nullptr, NN, nullptr, 0, nullptr, sscale);
    cudaEventRecord(eS0, s1);
    mma_gemm<<<dim3(16, 32), 256, SMEM_TOTAL, s1>>>(qt_h + sNC, qt_l + sNC, kt_h + sNC, kt_l + sNC,
        CC, CC, CC, s_ptr + sSS, nullptr, nullptr, NN, nullptr, 0, nullptr, sscale);
    cudaEventRecord(eS1, s1);

    // s2: softmax per batch (overlaps S_b1 / O_b0)
    cudaStreamWaitEvent(s2, eS0, 0);
    softmax_kernel<<<NN, 256, 0, s2>>>(s_ptr, p_h, p_l);
    cudaEventRecord(eSm0, s2);
    cudaStreamWaitEvent(s2, eS1, 0);
    softmax_kernel<<<NN, 256, 0, s2>>>(s_ptr + sSS, p_h + sSS, p_l + sSS);
    cudaEventRecord(eSm1, s2);

    // s1: O_b0 + final_b0 (needs sm0, v)
    cudaStreamWaitEvent(s1, eSm0, 0);
    cudaStreamWaitEvent(s1, eV, 0);
    mma_gemm<<<dim3(2, 32), 256, SMEM_TOTAL, s1>>>(p_h, p_l, v_h, v_l, NN, NN, NN,
        nullptr, ot_h, ot_l, CC, nullptr, 0, nullptr, 1.f);
    mma_gemm<<<dim3(16, 4), 256, SMEM_TOTAL, s1>>>(wo_h, wo_l, ot_h, ot_l, CC, CC, CC,
        out, nullptr, nullptr, NN, bo, 1, x, 1.f);
    cudaEventRecord(eDone1, s1);

    // s2: O_b1 + final_b1 (sm1 + v in-stream; overlaps O_b0)
    mma_gemm<<<dim3(2, 32), 256, SMEM_TOTAL, s2>>>(p_h + sSS, p_l + sSS, v_h + sCN, v_l + sCN,
        NN, NN, NN, nullptr, ot_h + sNC, ot_l + sNC, CC, nullptr, 0, nullptr, 1.f);
    mma_gemm<<<dim3(16, 4), 256, SMEM_TOTAL, s2>>>(wo_h, wo_l, ot_h + sNC, ot_l + sNC, CC, CC, CC,
        out + sCN, nullptr, nullptr, NN, bo, 1, x + sCN, 1.f);
    cudaEventRecord(eDone2, s2);

    // join back to default stream
    cudaStreamWaitEvent(0, eDone1, 0);
    cudaStreamWaitEvent(0, eDone2, 0);
}

// round 10
// speedup vs baseline: 1.0826x; 1.0826x over previous
#include <cuda_runtime.h>
#include <cuda_bf16.h>
#include <cstdint>
#include <math.h>

#define BB 2
#define CC 512
#define NN 4096
#define NGROUPS 32
#define CPG 16
#define EPS 1e-6f

typedef __nv_bfloat16 bf16;
typedef __nv_bfloat162 bf162;

// ---------------- scratch globals ----------------
__device__ bf16 g_ht_hi[(size_t)BB * NN * CC], g_ht_lo[(size_t)BB * NN * CC];   // h^T [b][n][c]
__device__ bf16 g_qt_hi[(size_t)BB * NN * CC], g_qt_lo[(size_t)BB * NN * CC];   // q^T [b][n][c]
__device__ bf16 g_kt_hi[(size_t)BB * NN * CC], g_kt_lo[(size_t)BB * NN * CC];
__device__ bf16 g_v_hi [(size_t)BB * CC * NN], g_v_lo [(size_t)BB * CC * NN];   // v [b][c][n]
__device__ bf16 g_ot_hi[(size_t)BB * NN * CC], g_ot_lo[(size_t)BB * NN * CC];   // o^T [b][n][c]
__device__ bf16 g_wq_hi[CC * CC], g_wq_lo[CC * CC];
__device__ bf16 g_wk_hi[CC * CC], g_wk_lo[CC * CC];
__device__ bf16 g_wv_hi[CC * CC], g_wv_lo[CC * CC];
__device__ bf16 g_wo_hi[CC * CC], g_wo_lo[CC * CC];
__device__ float g_s[(size_t)BB * NN * NN];                                      // logits
__device__ bf16 g_p_hi[(size_t)BB * NN * NN], g_p_lo[(size_t)BB * NN * NN];     // probs

// ---------------- PTX helpers ----------------
__device__ __forceinline__ uint32_t smem_u32(const void* p) {
    uint32_t a;
    asm("{ .reg .u64 t; cvta.to.shared.u64 t, %1; cvt.u32.u64 %0, t; }" : "=r"(a) : "l"(p));
    return a;
}
__device__ __forceinline__ void cp16(uint32_t saddr, const void* g) {
    asm volatile("cp.async.cg.shared.global [%0], [%1], 16;" :: "r"(saddr), "l"(g) : "memory");
}
#define CP_COMMIT() asm volatile("cp.async.commit_group;" ::: "memory")
#define CP_WAIT(n)  asm volatile("cp.async.wait_group %0;" :: "n"(n) : "memory")

__device__ __forceinline__ void ldm_x4(uint32_t* r, uint32_t addr) {
    asm volatile("ldmatrix.sync.aligned.m8n8.x4.shared.b16 {%0,%1,%2,%3}, [%4];"
        : "=r"(r[0]), "=r"(r[1]), "=r"(r[2]), "=r"(r[3]) : "r"(addr));
}
__device__ __forceinline__ void mma_bf16(float* d, const uint32_t* a, const uint32_t* b) {
    asm volatile("mma.sync.aligned.m16n8k16.row.col.f32.bf16.bf16.f32 "
        "{%0,%1,%2,%3}, {%4,%5,%6,%7}, {%8,%9}, {%0,%1,%2,%3};"
        : "+f"(d[0]), "+f"(d[1]), "+f"(d[2]), "+f"(d[3])
        : "r"(a[0]), "r"(a[1]), "r"(a[2]), "r"(a[3]), "r"(b[0]), "r"(b[1]));
}
#define SWZ64(o) ((o) ^ (((o) >> 3) & 0x30))

// ---------------- GroupNorm -> h^T hi/lo ----------------
__global__ void gn_kernel(const float* __restrict__ x,
                          const float* __restrict__ gamma,
                          const float* __restrict__ beta) {
    __shared__ float tile[16][257];
    __shared__ float red[8], red2[8];
    __shared__ float sga[16], sbe[16], s_mean, s_rstd;
    const int bg = blockIdx.x, b = bg >> 5, g = bg & 31;
    const size_t xbase = ((size_t)b * CC + (size_t)g * CPG) * NN;
    const float* xp = x + xbase;
    const int tid = threadIdx.x;
    if (tid < 16) { sga[tid] = gamma[g * CPG + tid]; sbe[tid] = beta[g * CPG + tid]; }

    float s = 0.f, ss = 0.f;
    for (int i = tid * 4; i < CPG * NN; i += 1024) {
        float4 v = *reinterpret_cast<const float4*>(xp + i);
        s += v.x + v.y + v.z + v.w;
        ss += v.x * v.x + v.y * v.y + v.z * v.z + v.w * v.w;
    }
    #pragma unroll
    for (int o = 16; o; o >>= 1) {
        s += __shfl_xor_sync(0xffffffffu, s, o);
        ss += __shfl_xor_sync(0xffffffffu, ss, o);
    }
    if ((tid & 31) == 0) { red[tid >> 5] = s; red2[tid >> 5] = ss; }
    __syncthreads();
    if (tid == 0) {
        float S = 0.f, SS = 0.f;
        for (int i = 0; i < 8; i++) { S += red[i]; SS += red2[i]; }
        float mean = S / (float)(CPG * NN);
        s_mean = mean;
        s_rstd = rsqrtf(SS / (float)(CPG * NN) - mean * mean + EPS);
    }
    __syncthreads();
    const float mean = s_mean, rstd = s_rstd;

    for (int n0 = 0; n0 < NN; n0 += 256) {
        __syncthreads();
        for (int i = tid; i < 16 * 256; i += 256) {
            int c = i >> 8, n = i & 255;
            tile[c][n] = xp[(size_t)c * NN + n0 + n];
        }
        __syncthreads();
        const int n = n0 + tid;
        __align__(16) bf162 hv[8], lv[8];
        #pragma unroll
        for (int c2 = 0; c2 < 8; c2++) {
            float v0 = (tile[2 * c2][tid] - mean) * rstd * sga[2 * c2] + sbe[2 * c2];
            float v1 = (tile[2 * c2 + 1][tid] - mean) * rstd * sga[2 * c2 + 1] + sbe[2 * c2 + 1];
            bf16 h0 = __float2bfloat16(v0), h1 = __float2bfloat16(v1);
            hv[c2] = __halves2bfloat162(h0, h1);
            lv[c2] = __halves2bfloat162(__float2bfloat16(v0 - __bfloat162float(h0)),
                                        __float2bfloat16(v1 - __bfloat162float(h1)));
        }
        const size_t dst = ((size_t)b * NN + n) * CC + (size_t)g * CPG;
        *reinterpret_cast<uint4*>(g_ht_hi + dst)     = reinterpret_cast<uint4*>(hv)[0];
        *reinterpret_cast<uint4*>(g_ht_hi + dst + 8) = reinterpret_cast<uint4*>(hv)[1];
        *reinterpret_cast<uint4*>(g_ht_lo + dst)     = reinterpret_cast<uint4*>(lv)[0];
        *reinterpret_cast<uint4*>(g_ht_lo + dst + 8) = reinterpret_cast<uint4*>(lv)[1];
    }
}

// ---------------- fused weight hi/lo decomposition ----------------
__global__ void decomp4_kernel(const float* __restrict__ w0, const float* __restrict__ w1,
                               const float* __restrict__ w2, const float* __restrict__ w3) {
    const int wsel = blockIdx.y;
    const float* src = (wsel == 0) ? w0 : (wsel == 1) ? w1 : (wsel == 2) ? w2 : w3;
    bf16* hi = (wsel == 0) ? g_wq_hi : (wsel == 1) ? g_wk_hi : (wsel == 2) ? g_wv_hi : g_wo_hi;
    bf16* lo = (wsel == 0) ? g_wq_lo : (wsel == 1) ? g_wk_lo : (wsel == 2) ? g_wv_lo : g_wo_lo;
    int i = blockIdx.x * blockDim.x + threadIdx.x;
    if (i >= (CC * CC) / 4) return;
    float4 v = reinterpret_cast<const float4*>(src)[i];
    bf16 h0 = __float2bfloat16(v.x), h1 = __float2bfloat16(v.y);
    bf16 h2 = __float2bfloat16(v.z), h3 = __float2bfloat16(v.w);
    __align__(8) bf162 hv[2] = { __halves2bfloat162(h0, h1), __halves2bfloat162(h2, h3) };
    __align__(8) bf162 lv[2] = {
        __halves2bfloat162(__float2bfloat16(v.x - __bfloat162float(h0)),
                           __float2bfloat16(v.y - __bfloat162float(h1))),
        __halves2bfloat162(__float2bfloat16(v.z - __bfloat162float(h2)),
                           __float2bfloat16(v.w - __bfloat162float(h3))) };
    *reinterpret_cast<uint2*>(hi + 4 * (size_t)i) = *reinterpret_cast<uint2*>(hv);
    *reinterpret_cast<uint2*>(lo + 4 * (size_t)i) = *reinterpret_cast<uint2*>(lv);
}

// ---------------- softmax (per batch) ----------------
__global__ void softmax_kernel(const float* __restrict__ sbase,
                               bf16* __restrict__ phi, bf16* __restrict__ plo) {
    __shared__ float row[NN];
    __shared__ float red[8];
    __shared__ float s_bcast;
    const size_t rbase = (size_t)blockIdx.x * NN;
    const float* sp = sbase + rbase;
    const int tid = threadIdx.x;

    float mx = -1e30f;
    for (int i = tid * 4; i < NN; i += 1024) {
        float4 v = *reinterpret_cast<const float4*>(sp + i);
        *reinterpret_cast<float4*>(row + i) = v;
        mx = fmaxf(fmaxf(v.x, v.y), fmaxf(fmaxf(v.z, v.w), mx));
    }
    #pragma unroll
    for (int o = 16; o; o >>= 1) mx = fmaxf(mx, __shfl_xor_sync(0xffffffffu, mx, o));
    if ((tid & 31) == 0) red[tid >> 5] = mx;
    __syncthreads();
    if (tid == 0) {
        float m = red[0];
        for (int i = 1; i < 8; i++) m = fmaxf(m, red[i]);
        s_bcast = m;
    }
    __syncthreads();
    mx = s_bcast;
    __syncthreads();

    float s = 0.f;
    for (int i = tid * 4; i < NN; i += 1024) {
        float4 v = *reinterpret_cast<float4*>(row + i);
        v.x = __expf(v.x - mx); v.y = __expf(v.y - mx);
        v.z = __expf(v.z - mx); v.w = __expf(v.w - mx);
        *reinterpret_cast<float4*>(row + i) = v;
        s += v.x + v.y + v.z + v.w;
    }
    #pragma unroll
    for (int o = 16; o; o >>= 1) s += __shfl_xor_sync(0xffffffffu, s, o);
    if ((tid & 31) == 0) red[tid >> 5] = s;
    __syncthreads();
    if (tid == 0) {
        float S = 0.f;
        for (int i = 0; i < 8; i++) S += red[i];
        s_bcast = 1.0f / S;
    }
    __syncthreads();
    const float inv = s_bcast;

    for (int i = tid * 4; i < NN; i += 1024) {
        float4 v = *reinterpret_cast<float4*>(row + i);
        float p0 = v.x * inv, p1 = v.y * inv, p2 = v.z * inv, p3 = v.w * inv;
        bf16 h0 = __float2bfloat16(p0), h1 = __float2bfloat16(p1);
        bf16 h2 = __float2bfloat16(p2), h3 = __float2bfloat16(p3);
        __align__(8) bf162 hv[2] = { __halves2bfloat162(h0, h1), __halves2bfloat162(h2, h3) };
        __align__(8) bf162 lv[2] = {
            __halves2bfloat162(__float2bfloat16(p0 - __bfloat162float(h0)),
                               __float2bfloat16(p1 - __bfloat162float(h1))),
            __halves2bfloat162(__float2bfloat16(p2 - __bfloat162float(h2)),
                               __float2bfloat16(p3 - __bfloat162float(h3))) };
        *reinterpret_cast<uint2*>(phi + rbase + i) = *reinterpret_cast<uint2*>(hv);
        *reinterpret_cast<uint2*>(plo + rbase + i) = *reinterpret_cast<uint2*>(lv);
    }
}

// ---------------- HMMA bf16x3 GEMM core: 128x128, BK=32, 3-stage, occ 2 -----
#define TILE_B 8192                       // 128 rows x 32 cols bf16 (64B rows, SW64)
#define STAGE_B (4 * TILE_B)              // Ahi, Alo, Bhi, Blo = 32KB
#define NSTAGE 3
#define SMEM_TOTAL (NSTAGE * STAGE_B)     // 98304

__device__ __forceinline__ void load_tile_async(const bf16* __restrict__ src, int row0,
                                                int ld, int k0, uint32_t sdst, int tid) {
    #pragma unroll
    for (int i = 0; i < 2; i++) {
        int c = tid + i * 256;
        int r = c >> 2, ck = c & 3;
        cp16(sdst + SWZ64((uint32_t)(r * 64 + ck * 16)),
             src + (size_t)(row0 + r) * ld + k0 + ck * 8);
    }
}

__device__ __forceinline__ void gemm_core(
        const bf16* __restrict__ pAh, const bf16* __restrict__ pAl,
        const bf16* __restrict__ pBh, const bf16* __restrict__ pBl,
        int lda, int ldb, int K, int m0, int n0,
        float* __restrict__ Cf, bf16* __restrict__ Chi, bf16* __restrict__ Clo,
        int ldc, const float* __restrict__ bias, int bias_mode,
        const float* __restrict__ resid, float scale, char* smem) {
    const uint32_t sb = smem_u32(smem);
    const int tid = threadIdx.x, wid = tid >> 5, lane = tid & 31;
    const int wm0 = (wid & 1) * 64, wn0 = (wid >> 1) * 32;
    const int NC = K >> 5;
    float acc[4][4][4] = {};

    load_tile_async(pAh, m0, lda, 0, sb, tid);
    load_tile_async(pAl, m0, lda, 0, sb + TILE_B, tid);
    load_tile_async(pBh, n0, ldb, 0, sb + 2 * TILE_B, tid);
    load_tile_async(pBl, n0, ldb, 0, sb + 3 * TILE_B, tid);
    CP_COMMIT();
    load_tile_async(pAh, m0, lda, 32, sb + STAGE_B, tid);
    load_tile_async(pAl, m0, lda, 32, sb + STAGE_B + TILE_B, tid);
    load_tile_async(pBh, n0, ldb, 32, sb + STAGE_B + 2 * TILE_B, tid);
    load_tile_async(pBl, n0, ldb, 32, sb + STAGE_B + 3 * TILE_B, tid);
    CP_COMMIT();

    int st = 0;
    for (int c = 0; c < NC; c++) {
        if (c + 1 < NC) { CP_WAIT(1); } else { CP_WAIT(0); }
        __syncthreads();
        if (c + 2 < NC) {
            int st2 = st + 2; if (st2 >= NSTAGE) st2 -= NSTAGE;
            uint32_t base = sb + st2 * STAGE_B;
            const int k0 = (c + 2) << 5;
            load_tile_async(pAh, m0, lda, k0, base, tid);
            load_tile_async(pAl, m0, lda, k0, base + TILE_B, tid);
            load_tile_async(pBh, n0, ldb, k0, base + 2 * TILE_B, tid);
            load_tile_async(pBl, n0, ldb, k0, base + 3 * TILE_B, tid);
            CP_COMMIT();
        }

        const uint32_t base = sb + st * STAGE_B;
        #pragma unroll
        for (int ks = 0; ks < 2; ks++) {
            uint32_t bhi[2][4], blo[2][4];
            #pragma unroll
            for (int nt2 = 0; nt2 < 2; nt2++) {
                const uint32_t off = SWZ64((uint32_t)(
                    (wn0 + nt2 * 16 + ((lane >> 4) & 1) * 8 + (lane & 7)) * 64 +
                    ks * 32 + ((lane >> 3) & 1) * 16));
                ldm_x4(bhi[nt2], base + 2 * TILE_B + off);
                ldm_x4(blo[nt2], base + 3 * TILE_B + off);
            }
            #pragma unroll
            for (int mt = 0; mt < 4; mt++) {
                uint32_t ahi[4], alo[4];
                const uint32_t off = SWZ64((uint32_t)(
                    (wm0 + mt * 16 + (lane & 15)) * 64 + ks * 32 + (lane >> 4) * 16));
                ldm_x4(ahi, base + off);
                ldm_x4(alo, base + TILE_B + off);
                #pragma unroll
                for (int nt = 0; nt < 4; nt++) {
                    const uint32_t* bh = &bhi[nt >> 1][(nt & 1) * 2];
                    const uint32_t* bl = &blo[nt >> 1][(nt & 1) * 2];
                    mma_bf16(acc[mt][nt], ahi, bh);
                    mma_bf16(acc[mt][nt], ahi, bl);
                    mma_bf16(acc[mt][nt], alo, bh);
                }
            }
        }
        st++; if (st >= NSTAGE) st = 0;
    }

    // epilogue
    const int r0 = lane >> 2, cp2 = (lane & 3) * 2;
    #pragma unroll
    for (int mt = 0; mt < 4; mt++) {
        #pragma unroll
        for (int half = 0; half < 2; half++) {
            const int gm = m0 + wm0 + mt * 16 + r0 + half * 8;
            const float bm = (bias_mode == 1) ? bias[gm] : 0.f;
            #pragma unroll
            for (int nt = 0; nt < 4; nt++) {
                const int gn = n0 + wn0 + nt * 8 + cp2;
                float v0 = acc[mt][nt][half * 2 + 0] * scale + bm;
                float v1 = acc[mt][nt][half * 2 + 1] * scale + bm;
                if (bias_mode == 2) { v0 += bias[gn]; v1 += bias[gn + 1]; }
                const size_t idx = (size_t)gm * ldc + gn;
                if (Cf) {
                    if (resid) { v0 += resid[idx]; v1 += resid[idx + 1]; }
                    float2 o = { v0, v1 };
                    *reinterpret_cast<float2*>(Cf + idx) = o;
                } else {
                    bf16 h0 = __float2bfloat16(v0), h1 = __float2bfloat16(v1);
                    bf162 hv = __halves2bfloat162(h0, h1);
                    bf162 lv = __halves2bfloat162(__float2bfloat16(v0 - __bfloat162float(h0)),
                                                  __float2bfloat16(v1 - __bfloat162float(h1)));
                    *reinterpret_cast<bf162*>(Chi + idx) = hv;
                    *reinterpret_cast<bf162*>(Clo + idx) = lv;
                }
            }
        }
    }
}

// Generic single-job wrapper (batch pre-offset on host)
__global__ void __launch_bounds__(256, 2)
mma_gemm(const bf16* __restrict__ Ah, const bf16* __restrict__ Al,
         const bf16* __restrict__ Bh, const bf16* __restrict__ Bl,
         int lda, int ldb, int K,
         float* __restrict__ Cf, bf16* __restrict__ Chi, bf16* __restrict__ Clo,
         int ldc, const float* __restrict__ bias, int bias_mode,
         const float* __restrict__ resid, float scale) {
    extern __shared__ __align__(1024) char smem[];
    gemm_core(Ah, Al, Bh, Bl, lda, ldb, K, blockIdx.y * 128, blockIdx.x * 128,
              Cf, Chi, Clo, ldc, bias, bias_mode, resid, scale, smem);
}

// Q/K projections: grid (4, 32, 4): z -> (b, op)
__global__ void __launch_bounds__(256, 2)
qk_gemm(const float* __restrict__ bq, const float* __restrict__ bk) {
    extern __shared__ __align__(1024) char smem[];
    const int b = blockIdx.z >> 1, op = blockIdx.z & 1;
    const size_t sNC = (size_t)NN * CC;
    const bf16* hth = g_ht_hi + (size_t)b * sNC;
    const bf16* htl = g_ht_lo + (size_t)b * sNC;
    const bf16* wh = op ? g_wk_hi : g_wq_hi;
    const bf16* wl = op ? g_wk_lo : g_wq_lo;
    bf16* ch = (op ? g_kt_hi : g_qt_hi) + (size_t)b * sNC;
    bf16* cl = (op ? g_kt_lo : g_qt_lo) + (size_t)b * sNC;
    gemm_core(hth, htl, wh, wl, CC, CC, CC, blockIdx.y * 128, blockIdx.x * 128,
              nullptr, ch, cl, CC, op ? bk : bq, 2, nullptr, 1.f, smem);
}

// V projection: grid (32, 4, 2): z = b
__global__ void __launch_bounds__(256, 2)
v_gemm(const float* __restrict__ bv) {
    extern __shared__ __align__(1024) char smem[];
    const int b = blockIdx.z;
    const size_t sNC = (size_t)NN * CC, sCN = (size_t)CC * NN;
    gemm_core(g_wv_hi, g_wv_lo,
              g_ht_hi + (size_t)b * sNC, g_ht_lo + (size_t)b * sNC,
              CC, CC, CC, blockIdx.y * 128, blockIdx.x * 128,
              nullptr, g_v_hi + (size_t)b * sCN, g_v_lo + (size_t)b * sCN,
              NN, bv, 1, nullptr, 1.f, smem);
}

// ---------------- launch ----------------
#define SYM(p, s) do { void* _t = nullptr; cudaGetSymbolAddress(&_t, s); p = (decltype(p))_t; } while (0)

extern "C" void kernel_launch(void* const* d_in, const int* in_sizes, int n_in,
                              void* d_out, int out_size) {
    const float* x     = (const float*)d_in[0];
    const float* gamma = (const float*)d_in[1];
    const float* beta  = (const float*)d_in[2];
    const float* wq = (const float*)d_in[3];
    const float* bq = (const float*)d_in[4];
    const float* wk = (const float*)d_in[5];
    const float* bk = (const float*)d_in[6];
    const float* wv = (const float*)d_in[7];
    const float* bv = (const float*)d_in[8];
    const float* wo = (const float*)d_in[9];
    const float* bo = (const float*)d_in[10];
    float* out = (float*)d_out;

    bf16 *qt_h, *qt_l, *kt_h, *kt_l, *v_h, *v_l, *ot_h, *ot_l;
    bf16 *wo_h, *wo_l, *p_h, *p_l;
    float* s_ptr;
    SYM(qt_h, g_qt_hi); SYM(qt_l, g_qt_lo);
    SYM(kt_h, g_kt_hi); SYM(kt_l, g_kt_lo);
    SYM(v_h, g_v_hi);   SYM(v_l, g_v_lo);
    SYM(ot_h, g_ot_hi); SYM(ot_l, g_ot_lo);
    SYM(wo_h, g_wo_hi); SYM(wo_l, g_wo_lo);
    SYM(p_h, g_p_hi);   SYM(p_l, g_p_lo);
    SYM(s_ptr, g_s);

    static bool inited = false;
    static cudaStream_t s1, s2;
    static cudaEvent_t eFork, eGn, eD1, eV, eS0, eS1, eSm0, eDone1, eDone2;
    if (!inited) {
        cudaStreamCreateWithFlags(&s1, cudaStreamNonBlocking);
        cudaStreamCreateWithFlags(&s2, cudaStreamNonBlocking);
        cudaEventCreateWithFlags(&eFork,  cudaEventDisableTiming);
        cudaEventCreateWithFlags(&eGn,    cudaEventDisableTiming);
        cudaEventCreateWithFlags(&eD1,    cudaEventDisableTiming);
        cudaEventCreateWithFlags(&eV,     cudaEventDisableTiming);
        cudaEventCreateWithFlags(&eS0,    cudaEventDisableTiming);
        cudaEventCreateWithFlags(&eS1,    cudaEventDisableTiming);
        cudaEventCreateWithFlags(&eSm0,   cudaEventDisableTiming);
        cudaEventCreateWithFlags(&eDone1, cudaEventDisableTiming);
        cudaEventCreateWithFlags(&eDone2, cudaEventDisableTiming);
        cudaFuncSetAttribute(mma_gemm, cudaFuncAttributeMaxDynamicSharedMemorySize, SMEM_TOTAL);
        cudaFuncSetAttribute(qk_gemm,  cudaFuncAttributeMaxDynamicSharedMemorySize, SMEM_TOTAL);
        cudaFuncSetAttribute(v_gemm,   cudaFuncAttributeMaxDynamicSharedMemorySize, SMEM_TOTAL);
        inited = true;
    }

    const size_t sNC = (size_t)NN * CC, sCN = (size_t)CC * NN, sSS = (size_t)NN * NN;

    // fork both worker streams off the (capturing) default stream
    cudaEventRecord(eFork, 0);
    cudaStreamWaitEvent(s1, eFork, 0);
    cudaStreamWaitEvent(s2, eFork, 0);

    // s2: groupnorm  |  s1: weight decomposition (independent)
    gn_kernel<<<BB * NGROUPS, 256, 0, s2>>>(x, gamma, beta);
    cudaEventRecord(eGn, s2);
    decomp4_kernel<<<dim3((CC * CC / 4 + 255) / 256, 4), 256, 0, s1>>>(wq, wk, wv, wo);
    cudaEventRecord(eD1, s1);

    // s1: Q,K projections (needs gn + decomp)
    cudaStreamWaitEvent(s1, eGn, 0);
    qk_gemm<<<dim3(4, 32, 4), 256, SMEM_TOTAL, s1>>>(bq, bk);

    // s2: V projection (needs gn [in-stream] + decomp)
    cudaStreamWaitEvent(s2, eD1, 0);
    v_gemm<<<dim3(32, 4, 2), 256, SMEM_TOTAL, s2>>>(bv);
    cudaEventRecord(eV, s2);

    // s1: S per batch
    const float sscale = 0.044194173824159216f;
    mma_gemm<<<dim3(32, 32), 256, SMEM_TOTAL, s1>>>(qt_h, qt_l, kt_h, kt_l, CC, CC, CC,
        s_ptr, nullptr, nullptr, NN, nullptr, 0, nullptr, sscale);
    cudaEventRecord(eS0, s1);
    mma_gemm<<<dim3(32, 32), 256, SMEM_TOTAL, s1>>>(qt_h + sNC, qt_l + sNC, kt_h + sNC, kt_l + sNC,
        CC, CC, CC, s_ptr + sSS, nullptr, nullptr, NN, nullptr, 0, nullptr, sscale);
    cudaEventRecord(eS1, s1);

    // s2: softmax per batch (overlaps S_b1 / O_b0)
    cudaStreamWaitEvent(s2, eS0, 0);
    softmax_kernel<<<NN, 256, 0, s2>>>(s_ptr, p_h, p_l);
    cudaEventRecord(eSm0, s2);
    cudaStreamWaitEvent(s2, eS1, 0);
    softmax_kernel<<<NN, 256, 0, s2>>>(s_ptr + sSS, p_h + sSS, p_l + sSS);

    // s1: O_b0 + final_b0 (needs sm0, v)
    cudaStreamWaitEvent(s1, eSm0, 0);
    cudaStreamWaitEvent(s1, eV, 0);
    mma_gemm<<<dim3(4, 32), 256, SMEM_TOTAL, s1>>>(p_h, p_l, v_h, v_l, NN, NN, NN,
        nullptr, ot_h, ot_l, CC, nullptr, 0, nullptr, 1.f);
    mma_gemm<<<dim3(32, 4), 256, SMEM_TOTAL, s1>>>(wo_h, wo_l, ot_h, ot_l, CC, CC, CC,
        out, nullptr, nullptr, NN, bo, 1, x, 1.f);
    cudaEventRecord(eDone1, s1);

    // s2: O_b1 + final_b1 (sm1 + v in-stream; overlaps O_b0)
    mma_gemm<<<dim3(4, 32), 256, SMEM_TOTAL, s2>>>(p_h + sSS, p_l + sSS, v_h + sCN, v_l + sCN,
        NN, NN, NN, nullptr, ot_h + sNC, ot_l + sNC, CC, nullptr, 0, nullptr, 1.f);
    mma_gemm<<<dim3(32, 4), 256, SMEM_TOTAL, s2>>>(wo_h, wo_l, ot_h + sNC, ot_l + sNC, CC, CC, CC,
        out + sCN, nullptr, nullptr, NN, bo, 1, x + sCN, 1.f);
    cudaEventRecord(eDone2, s2);

    // join back to default stream
    cudaStreamWaitEvent(0, eDone1, 0);
    cudaStreamWaitEvent(0, eDone2, 0);
}